// round 8
// baseline (speedup 1.0000x reference)
#include <cuda_runtime.h>
#include <cuda_fp16.h>

static constexpr int TOK   = 64;     // tokens per sequence
static constexpr int D     = 512;    // embedding dim
static constexpr int NC    = 64;     // classes
static constexpr int QN    = 2048;   // queries
static constexpr int SN    = 4096;   // supports
static constexpr int VOCAB = 32000;

// GEMM config: proto_raw[64 x 512] = W[64 x 32000] @ table_h[32000 x 512]
static constexpr int KS     = 25;            // K splits
static constexpr int KCHUNK = VOCAB / KS;    // 1280
static constexpr int NT     = 4;             // N tiles of 128  (grid = 100)

// Scratch (allocation-free rule: __device__ globals)
__device__ __align__(16) __half g_table_h[VOCAB * D]; // fp16 shadow (32.8 MB)
__device__ __align__(16) __half g_W[NC * VOCAB];      // class-token histogram (4.1 MB)
__device__ float g_proto[NC * D];   // RAW token sums per class (64*cnt times the mean)
__device__ float g_cnt[NC];         // per-class support-row counts
__device__ float g_qemb[QN * D];    // query embeddings (mean-pooled)
__device__ float g_q2[QN];          // ||q||^2

__device__ __forceinline__ unsigned smem_u32(const void* p) {
    unsigned a;
    asm("{ .reg .u64 t; cvta.to.shared.u64 t, %1; cvt.u32.u64 %0, t; }"
        : "=r"(a) : "l"(p));
    return a;
}

// ---------------------------------------------------------------- kernel 1
// Convert table fp32 -> fp16 shadow; zero W / proto / cnt scratch.
// Grid has 2.048M threads: covers 1.024M u32 of W, 32768 proto floats, 64 cnts.
__global__ __launch_bounds__(256) void k_convert(const float* __restrict__ t)
{
    const int i = blockIdx.x * blockDim.x + threadIdx.x;  // 8-elem group id
    if (i < NC * VOCAB / 2) ((unsigned*)g_W)[i] = 0u;
    if (i < NC * D)         g_proto[i] = 0.0f;
    if (i < NC)             g_cnt[i]   = 0.0f;

    const float4* s = (const float4*)t;
    float4 a = s[2 * i];
    float4 b = s[2 * i + 1];
    __half2 h0 = __floats2half2_rn(a.x, a.y);
    __half2 h1 = __floats2half2_rn(a.z, a.w);
    __half2 h2 = __floats2half2_rn(b.x, b.y);
    __half2 h3 = __floats2half2_rn(b.z, b.w);
    uint4 o;
    o.x = *(const unsigned*)&h0;
    o.y = *(const unsigned*)&h1;
    o.z = *(const unsigned*)&h2;
    o.w = *(const unsigned*)&h3;
    ((uint4*)g_table_h)[i] = o;
}

// ---------------------------------------------------------------- kernel 2
// Histogram: one thread per support token. W[c][v] += 1 (fp16 exact, counts
// are tiny). Also counts support rows per class (one lane per row).
__global__ __launch_bounds__(256) void k_hist(
    const int* __restrict__ s_toks,
    const int* __restrict__ labels)
{
    const int t   = blockIdx.x * blockDim.x + threadIdx.x;  // 0 .. SN*TOK
    const int row = t >> 6;
    const int c   = labels[row];
    const int v   = s_toks[t];
    const int idx = c * VOCAB + v;
    __half2* p = (__half2*)(g_W + (idx & ~1));
    const __half2 one = (idx & 1) ? __halves2half2(__ushort_as_half(0), __float2half(1.0f))
                                  : __halves2half2(__float2half(1.0f), __ushort_as_half(0));
    atomicAdd(p, one);
    if ((t & 63) == 0) atomicAdd(&g_cnt[c], 1.0f);
}

// ---------------------------------------------------------------- kernel 3
// Query gather (R3-proven loop): one block per query row; thread t owns dims
// [4t, 4t+4) via one uint2 per token; 64 serially-unrolled token loads.
__global__ __launch_bounds__(128) void k_gather(const int* __restrict__ toks)
{
    const int row = blockIdx.x;
    __shared__ int sh_tok[TOK];
    if (threadIdx.x < TOK)
        sh_tok[threadIdx.x] = toks[(size_t)row * TOK + threadIdx.x];
    __syncthreads();

    float a0 = 0.f, a1 = 0.f, a2 = 0.f, a3 = 0.f;
    #pragma unroll 8
    for (int j = 0; j < TOK; ++j) {
        const uint2* r = (const uint2*)(g_table_h + (size_t)sh_tok[j] * D);
        uint2 v = r[threadIdx.x];
        float2 f0 = __half22float2(*(const __half2*)&v.x);
        float2 f1 = __half22float2(*(const __half2*)&v.y);
        a0 += f0.x; a1 += f0.y; a2 += f1.x; a3 += f1.y;
    }
    const float s = 1.0f / (float)TOK;
    a0 *= s; a1 *= s; a2 *= s; a3 *= s;
    ((float4*)(g_qemb + (size_t)row * D))[threadIdx.x] =
        make_float4(a0, a1, a2, a3);

    float qq = a0*a0 + a1*a1 + a2*a2 + a3*a3;
    #pragma unroll
    for (int o = 16; o > 0; o >>= 1)
        qq += __shfl_down_sync(0xFFFFFFFFu, qq, o);
    __shared__ float sp[4];
    if ((threadIdx.x & 31) == 0) sp[threadIdx.x >> 5] = qq;
    __syncthreads();
    if (threadIdx.x == 0) g_q2[row] = sp[0] + sp[1] + sp[2] + sp[3];
}

// ---------------------------------------------------------------- kernel 4
// Split-K tensor-core GEMM: block = (n-tile of 128, k-chunk of 1280).
// 4 warps; warp w computes rows [16w,16w+16) x 128 cols via mma.m16n8k16.
__global__ __launch_bounds__(128) void k_pgemm()
{
    __shared__ __half sA[64 * 24];    // 64x16 W tile, row stride 24 halves
    __shared__ __half sB[16 * 136];   // 16x128 table tile, row stride 136

    const int bn = (blockIdx.x & (NT - 1)) * 128;       // n offset
    const int k0 = (blockIdx.x / NT) * KCHUNK;          // k offset
    const int tid  = threadIdx.x;
    const int warp = tid >> 5;
    const int lane = tid & 31;
    const int g    = lane >> 2;       // 0..7
    const int tg   = lane & 3;        // 0..3

    // Staging-load addressing
    const int arow  = tid >> 1;             // 0..63  (A: 64 rows x 16 halves)
    const int acol8 = (tid & 1) * 8;        // 0 or 8
    const int brow  = tid >> 3;             // 0..15  (B: 16 rows x 128 halves)
    const int bcol  = (tid & 7) * 16;       // 0,16,...,112  (16 halves/thread)

    // ldmatrix addressing
    const int am = lane >> 3, ar = lane & 7;
    const unsigned aAddr = smem_u32(sA + (warp * 16 + ar + 8 * (am & 1)) * 24
                                       + 8 * (am >> 1));
    const unsigned bRowAddr = smem_u32(sB + (lane & 15) * 136);

    float acc[16][4];
    #pragma unroll
    for (int s = 0; s < 16; ++s)
        acc[s][0] = acc[s][1] = acc[s][2] = acc[s][3] = 0.0f;

    for (int kk = 0; kk < KCHUNK; kk += 16) {
        uint4 va  = *(const uint4*)(g_W + (size_t)arow * VOCAB + k0 + kk + acol8);
        const __half* brp = g_table_h + (size_t)(k0 + kk + brow) * D + bn + bcol;
        uint4 vb0 = *(const uint4*)(brp);
        uint4 vb1 = *(const uint4*)(brp + 8);
        __syncthreads();                       // prior step's smem reads done
        *(uint4*)(sA + arow * 24 + acol8)  = va;
        *(uint4*)(sB + brow * 136 + bcol)  = vb0;
        *(uint4*)(sB + brow * 136 + bcol + 8) = vb1;
        __syncthreads();

        unsigned a0, a1, a2, a3;
        asm volatile("ldmatrix.sync.aligned.m8n8.x4.shared.b16 {%0,%1,%2,%3}, [%4];"
                     : "=r"(a0), "=r"(a1), "=r"(a2), "=r"(a3) : "r"(aAddr));
        #pragma unroll
        for (int s = 0; s < 16; ++s) {
            unsigned b0, b1;
            asm volatile("ldmatrix.sync.aligned.m8n8.x2.trans.shared.b16 {%0,%1}, [%2];"
                         : "=r"(b0), "=r"(b1) : "r"(bRowAddr + s * 16));
            asm volatile(
                "mma.sync.aligned.m16n8k16.row.col.f32.f16.f16.f32 "
                "{%0,%1,%2,%3}, {%4,%5,%6,%7}, {%8,%9}, {%0,%1,%2,%3};"
                : "+f"(acc[s][0]), "+f"(acc[s][1]), "+f"(acc[s][2]), "+f"(acc[s][3])
                : "r"(a0), "r"(a1), "r"(a2), "r"(a3), "r"(b0), "r"(b1));
        }
    }

    // Epilogue: split-K accumulate into raw proto sums.
    #pragma unroll
    for (int s = 0; s < 16; ++s) {
        const int col = bn + s * 8 + tg * 2;
        float* r0 = g_proto + (warp * 16 + g) * D + col;
        float* r1 = g_proto + (warp * 16 + g + 8) * D + col;
        atomicAdd(r0 + 0, acc[s][0]);
        atomicAdd(r0 + 1, acc[s][1]);
        atomicAdd(r1 + 0, acc[s][2]);
        atomicAdd(r1 + 1, acc[s][3]);
    }
}

// ---------------------------------------------------------------- kernel 5
// 16 queries x 64 classes per block. Raw sums: p = raw/(64*max(cnt,1)).
__global__ __launch_bounds__(256) void k_out(float* __restrict__ out)
{
    const int c  = threadIdx.x & 63;
    const int g  = threadIdx.x >> 6;              // 0..3
    const int q0 = blockIdx.x * 16 + g * 4;

    const float4* pr = (const float4*)(g_proto + (size_t)c * D);
    const float4* qa = (const float4*)(g_qemb + (size_t)(q0 + 0) * D);
    const float4* qb = (const float4*)(g_qemb + (size_t)(q0 + 1) * D);
    const float4* qc = (const float4*)(g_qemb + (size_t)(q0 + 2) * D);
    const float4* qd = (const float4*)(g_qemb + (size_t)(q0 + 3) * D);

    float d0 = 0.f, d1 = 0.f, d2 = 0.f, d3 = 0.f, pp = 0.f;
    #pragma unroll 4
    for (int i = 0; i < D / 4; ++i) {
        float4 p = pr[i];
        float4 a = qa[i], b = qb[i], x = qc[i], y = qd[i];
        pp += p.x*p.x + p.y*p.y + p.z*p.z + p.w*p.w;
        d0 += p.x*a.x + p.y*a.y + p.z*a.z + p.w*a.w;
        d1 += p.x*b.x + p.y*b.y + p.z*b.z + p.w*b.w;
        d2 += p.x*x.x + p.y*x.y + p.z*x.z + p.w*x.w;
        d3 += p.x*y.x + p.y*y.y + p.z*y.z + p.w*y.w;
    }
    const float inv  = 1.0f / (64.0f * fmaxf(g_cnt[c], 1.0f));
    const float p2   = pp * inv * inv;
    const float two_inv = 2.0f * inv;
    out[(size_t)(q0 + 0) * NC + c] = -(g_q2[q0 + 0] + p2 - two_inv * d0);
    out[(size_t)(q0 + 1) * NC + c] = -(g_q2[q0 + 1] + p2 - two_inv * d1);
    out[(size_t)(q0 + 2) * NC + c] = -(g_q2[q0 + 2] + p2 - two_inv * d2);
    out[(size_t)(q0 + 3) * NC + c] = -(g_q2[q0 + 3] + p2 - two_inv * d3);
}

// ----------------------------------------------------------------
extern "C" void kernel_launch(void* const* d_in, const int* in_sizes, int n_in,
                              void* d_out, int out_size)
{
    // JAX x64 disabled -> "int64" tensors are int32 on the wire.
    const int*   query   = (const int*)d_in[0];
    const int*   support = (const int*)d_in[1];
    const int*   labels  = (const int*)d_in[2];
    const float* table   = (const float*)d_in[3];
    float* out = (float*)d_out;

    k_convert<<<(VOCAB * D / 8) / 256, 256>>>(table);  // convert + zero scratch
    k_hist<<<SN * TOK / 256, 256>>>(support, labels);  // class-token histogram
    k_gather<<<QN, 128>>>(query);                      // query embeddings
    k_pgemm<<<NT * KS, 128>>>();                       // protos via tensor cores
    k_out<<<QN / 16, 256>>>(out);                      // distances
}

// round 9
// speedup vs baseline: 1.1479x; 1.1479x over previous
#include <cuda_runtime.h>
#include <cuda_fp16.h>

static constexpr int TOK   = 64;     // tokens per sequence
static constexpr int D     = 512;    // embedding dim
static constexpr int NC    = 64;     // classes
static constexpr int QN    = 2048;   // queries
static constexpr int SN    = 4096;   // supports
static constexpr int VOCAB = 32000;

// GEMM config: proto_raw[64 x 512] = W[64 x 32000] @ table_h[32000 x 512]
static constexpr int KS     = 125;           // K splits
static constexpr int KCHUNK = VOCAB / KS;    // 256
static constexpr int NT     = 4;             // N tiles of 128  (grid = 500)

// Scratch (allocation-free rule: __device__ globals)
__device__ __align__(16) __half g_table_h[VOCAB * D]; // fp16 shadow (32.8 MB)
__device__ __align__(16) __half g_W[NC * VOCAB];      // class-token histogram (4.1 MB)
__device__ __align__(16) float g_pp[KS * NC * D];     // split-K partials (16.4 MB)
__device__ float g_proto[NC * D];   // RAW token sums per class
__device__ float g_cnt[NC];         // per-class support-row counts
__device__ float g_qemb[QN * D];    // query embeddings (mean-pooled)
__device__ float g_q2[QN];          // ||q||^2

__device__ __forceinline__ unsigned smem_u32(const void* p) {
    unsigned a;
    asm("{ .reg .u64 t; cvta.to.shared.u64 t, %1; cvt.u32.u64 %0, t; }"
        : "=r"(a) : "l"(p));
    return a;
}

// ---------------------------------------------------------------- kernel 1
// Convert table fp32 -> fp16 shadow; zero W / cnt scratch.
__global__ __launch_bounds__(256) void k_convert(const float* __restrict__ t)
{
    const int i = blockIdx.x * blockDim.x + threadIdx.x;  // 8-elem group id
    if (i < NC * VOCAB / 2) ((unsigned*)g_W)[i] = 0u;
    if (i < NC)             g_cnt[i] = 0.0f;

    const float4* s = (const float4*)t;
    float4 a = s[2 * i];
    float4 b = s[2 * i + 1];
    __half2 h0 = __floats2half2_rn(a.x, a.y);
    __half2 h1 = __floats2half2_rn(a.z, a.w);
    __half2 h2 = __floats2half2_rn(b.x, b.y);
    __half2 h3 = __floats2half2_rn(b.z, b.w);
    uint4 o;
    o.x = *(const unsigned*)&h0;
    o.y = *(const unsigned*)&h1;
    o.z = *(const unsigned*)&h2;
    o.w = *(const unsigned*)&h3;
    ((uint4*)g_table_h)[i] = o;
}

// ---------------------------------------------------------------- kernel 2
// Histogram: one thread per support token. W[c][v] += 1 (fp16 exact).
__global__ __launch_bounds__(256) void k_hist(
    const int* __restrict__ s_toks,
    const int* __restrict__ labels)
{
    const int t   = blockIdx.x * blockDim.x + threadIdx.x;  // 0 .. SN*TOK
    const int row = t >> 6;
    const int c   = labels[row];
    const int v   = s_toks[t];
    const int idx = c * VOCAB + v;
    __half2* p = (__half2*)(g_W + (idx & ~1));
    const __half2 one = (idx & 1) ? __halves2half2(__ushort_as_half(0), __float2half(1.0f))
                                  : __halves2half2(__float2half(1.0f), __ushort_as_half(0));
    atomicAdd(p, one);
    if ((t & 63) == 0) atomicAdd(&g_cnt[c], 1.0f);
}

// ---------------------------------------------------------------- kernel 3
// Query gather (R3-proven loop): one block per query row; thread t owns dims
// [4t, 4t+4) via one uint2 per token; 64 serially-unrolled token loads.
__global__ __launch_bounds__(128) void k_gather(const int* __restrict__ toks)
{
    const int row = blockIdx.x;
    __shared__ int sh_tok[TOK];
    if (threadIdx.x < TOK)
        sh_tok[threadIdx.x] = toks[(size_t)row * TOK + threadIdx.x];
    __syncthreads();

    float a0 = 0.f, a1 = 0.f, a2 = 0.f, a3 = 0.f;
    #pragma unroll 8
    for (int j = 0; j < TOK; ++j) {
        const uint2* r = (const uint2*)(g_table_h + (size_t)sh_tok[j] * D);
        uint2 v = r[threadIdx.x];
        float2 f0 = __half22float2(*(const __half2*)&v.x);
        float2 f1 = __half22float2(*(const __half2*)&v.y);
        a0 += f0.x; a1 += f0.y; a2 += f1.x; a3 += f1.y;
    }
    const float s = 1.0f / (float)TOK;
    a0 *= s; a1 *= s; a2 *= s; a3 *= s;
    ((float4*)(g_qemb + (size_t)row * D))[threadIdx.x] =
        make_float4(a0, a1, a2, a3);

    float qq = a0*a0 + a1*a1 + a2*a2 + a3*a3;
    #pragma unroll
    for (int o = 16; o > 0; o >>= 1)
        qq += __shfl_down_sync(0xFFFFFFFFu, qq, o);
    __shared__ float sp[4];
    if ((threadIdx.x & 31) == 0) sp[threadIdx.x >> 5] = qq;
    __syncthreads();
    if (threadIdx.x == 0) g_q2[row] = sp[0] + sp[1] + sp[2] + sp[3];
}

// ---------------------------------------------------------------- kernel 4
// Split-K tensor-core GEMM, software-pipelined: block = (n-tile 128, k-chunk
// 256). 4 warps; warp w computes rows [16w,16w+16) x 128 cols (m16n8k16).
// Next k-tile is prefetched into registers while the current tile is in mma.
// Partials go to g_pp (plain stores; disjoint regions) — no hot atomics.
__global__ __launch_bounds__(128) void k_pgemm()
{
    __shared__ __half sA[64 * 24];    // 64x16 W tile, row stride 24 halves
    __shared__ __half sB[16 * 136];   // 16x128 table tile, row stride 136

    const int bn = (blockIdx.x & (NT - 1)) * 128;       // n offset
    const int kb = blockIdx.x / NT;                     // k-split index
    const int k0 = kb * KCHUNK;
    const int tid  = threadIdx.x;
    const int warp = tid >> 5;
    const int lane = tid & 31;
    const int g    = lane >> 2;       // 0..7
    const int tg   = lane & 3;        // 0..3

    // Staging-load addressing
    const int arow  = tid >> 1;             // 0..63  (A: 64 rows x 16 halves)
    const int acol8 = (tid & 1) * 8;        // 0 or 8
    const int brow  = tid >> 3;             // 0..15  (B: 16 rows x 128 halves)
    const int bcol  = (tid & 7) * 16;       // 0..112 (16 halves/thread)

    const __half* aSrc = g_W + (size_t)arow * VOCAB + k0 + acol8;
    const __half* bSrc = g_table_h + (size_t)(k0 + brow) * D + bn + bcol;

    // ldmatrix addressing
    const int am = lane >> 3, ar = lane & 7;
    const unsigned aAddr = smem_u32(sA + (warp * 16 + ar + 8 * (am & 1)) * 24
                                       + 8 * (am >> 1));
    const unsigned bRowAddr = smem_u32(sB + (lane & 15) * 136);

    float acc[16][4];
    #pragma unroll
    for (int s = 0; s < 16; ++s)
        acc[s][0] = acc[s][1] = acc[s][2] = acc[s][3] = 0.0f;

    // Prologue: tile 0 into registers.
    uint4 va  = *(const uint4*)(aSrc);
    uint4 vb0 = *(const uint4*)(bSrc);
    uint4 vb1 = *(const uint4*)(bSrc + 8);

    const int NITER = KCHUNK / 16;          // 16
    for (int it = 0; it < NITER; ++it) {
        __syncthreads();                    // prior step's smem reads done
        *(uint4*)(sA + arow * 24 + acol8)     = va;
        *(uint4*)(sB + brow * 136 + bcol)     = vb0;
        *(uint4*)(sB + brow * 136 + bcol + 8) = vb1;
        __syncthreads();

        // Prefetch next tile (clamped redundant re-load on last iter).
        const int kn = min((it + 1) * 16, KCHUNK - 16);
        va  = *(const uint4*)(aSrc + kn);
        vb0 = *(const uint4*)(bSrc + (size_t)kn * D);
        vb1 = *(const uint4*)(bSrc + (size_t)kn * D + 8);

        unsigned a0, a1, a2, a3;
        asm volatile("ldmatrix.sync.aligned.m8n8.x4.shared.b16 {%0,%1,%2,%3}, [%4];"
                     : "=r"(a0), "=r"(a1), "=r"(a2), "=r"(a3) : "r"(aAddr));
        #pragma unroll
        for (int s = 0; s < 16; ++s) {
            unsigned b0, b1;
            asm volatile("ldmatrix.sync.aligned.m8n8.x2.trans.shared.b16 {%0,%1}, [%2];"
                         : "=r"(b0), "=r"(b1) : "r"(bRowAddr + s * 16));
            asm volatile(
                "mma.sync.aligned.m16n8k16.row.col.f32.f16.f16.f32 "
                "{%0,%1,%2,%3}, {%4,%5,%6,%7}, {%8,%9}, {%0,%1,%2,%3};"
                : "+f"(acc[s][0]), "+f"(acc[s][1]), "+f"(acc[s][2]), "+f"(acc[s][3])
                : "r"(a0), "r"(a1), "r"(a2), "r"(a3), "r"(b0), "r"(b1));
        }
    }

    // Epilogue: plain stores to this split's private partial slice.
    float* base = g_pp + (size_t)kb * NC * D;
    #pragma unroll
    for (int s = 0; s < 16; ++s) {
        const int col = bn + s * 8 + tg * 2;
        *(float2*)(base + (warp * 16 + g) * D + col)     =
            make_float2(acc[s][0], acc[s][1]);
        *(float2*)(base + (warp * 16 + g + 8) * D + col) =
            make_float2(acc[s][2], acc[s][3]);
    }
}

// ---------------------------------------------------------------- kernel 5
// Reduce split-K partials: g_proto[i] = sum_s g_pp[s][i]. Fully coalesced.
__global__ __launch_bounds__(256) void k_reduce()
{
    const int i = blockIdx.x * blockDim.x + threadIdx.x;   // < NC*D
    float a = 0.0f;
    #pragma unroll 5
    for (int s = 0; s < KS; ++s) a += g_pp[(size_t)s * NC * D + i];
    g_proto[i] = a;
}

// ---------------------------------------------------------------- kernel 6
// 16 queries x 64 classes per block. Raw sums: p = raw/(64*max(cnt,1)).
__global__ __launch_bounds__(256) void k_out(float* __restrict__ out)
{
    const int c  = threadIdx.x & 63;
    const int g  = threadIdx.x >> 6;              // 0..3
    const int q0 = blockIdx.x * 16 + g * 4;

    const float4* pr = (const float4*)(g_proto + (size_t)c * D);
    const float4* qa = (const float4*)(g_qemb + (size_t)(q0 + 0) * D);
    const float4* qb = (const float4*)(g_qemb + (size_t)(q0 + 1) * D);
    const float4* qc = (const float4*)(g_qemb + (size_t)(q0 + 2) * D);
    const float4* qd = (const float4*)(g_qemb + (size_t)(q0 + 3) * D);

    float d0 = 0.f, d1 = 0.f, d2 = 0.f, d3 = 0.f, pp = 0.f;
    #pragma unroll 4
    for (int i = 0; i < D / 4; ++i) {
        float4 p = pr[i];
        float4 a = qa[i], b = qb[i], x = qc[i], y = qd[i];
        pp += p.x*p.x + p.y*p.y + p.z*p.z + p.w*p.w;
        d0 += p.x*a.x + p.y*a.y + p.z*a.z + p.w*a.w;
        d1 += p.x*b.x + p.y*b.y + p.z*b.z + p.w*b.w;
        d2 += p.x*x.x + p.y*x.y + p.z*x.z + p.w*x.w;
        d3 += p.x*y.x + p.y*y.y + p.z*y.z + p.w*y.w;
    }
    const float inv  = 1.0f / (64.0f * fmaxf(g_cnt[c], 1.0f));
    const float p2   = pp * inv * inv;
    const float two_inv = 2.0f * inv;
    out[(size_t)(q0 + 0) * NC + c] = -(g_q2[q0 + 0] + p2 - two_inv * d0);
    out[(size_t)(q0 + 1) * NC + c] = -(g_q2[q0 + 1] + p2 - two_inv * d1);
    out[(size_t)(q0 + 2) * NC + c] = -(g_q2[q0 + 2] + p2 - two_inv * d2);
    out[(size_t)(q0 + 3) * NC + c] = -(g_q2[q0 + 3] + p2 - two_inv * d3);
}

// ----------------------------------------------------------------
extern "C" void kernel_launch(void* const* d_in, const int* in_sizes, int n_in,
                              void* d_out, int out_size)
{
    // JAX x64 disabled -> "int64" tensors are int32 on the wire.
    const int*   query   = (const int*)d_in[0];
    const int*   support = (const int*)d_in[1];
    const int*   labels  = (const int*)d_in[2];
    const float* table   = (const float*)d_in[3];
    float* out = (float*)d_out;

    k_convert<<<(VOCAB * D / 8) / 256, 256>>>(table);  // convert + zero W/cnt
    k_hist<<<SN * TOK / 256, 256>>>(support, labels);  // class-token histogram
    k_gather<<<QN, 128>>>(query);                      // query embeddings
    k_pgemm<<<NT * KS, 128>>>();                       // protos via tensor cores
    k_reduce<<<NC * D / 256, 256>>>();                 // fold split-K partials
    k_out<<<QN / 16, 256>>>(out);                      // distances
}

// round 10
// speedup vs baseline: 1.1700x; 1.0193x over previous
#include <cuda_runtime.h>
#include <cuda_fp16.h>

static constexpr int TOK   = 64;     // tokens per sequence
static constexpr int D     = 512;    // embedding dim
static constexpr int NC    = 64;     // classes
static constexpr int QN    = 2048;   // queries
static constexpr int SN    = 4096;   // supports
static constexpr int VOCAB = 32000;

// GEMM: proto_raw[64 x 32000-hist] @ table_h[32000 x 512]
static constexpr int KS     = 200;           // K splits
static constexpr int KCHUNK = VOCAB / KS;    // 160
static constexpr int NITER  = KCHUNK / 16;   // 10
static constexpr int NT     = 4;             // N tiles of 128  (grid = 800)

// k_front role boundaries (block index)
static constexpr int FB_GATHER = 1024;               // 1024 blocks x 2 query rows
static constexpr int FB_CONV   = FB_GATHER + 8000;   // 8000 convert blocks
static constexpr int FB_HIST   = FB_CONV + 1024;     // 1024 hist blocks

// Scratch (__device__ globals; zero-initialized at module load).
// INVARIANT: g_W and g_cnt are ZERO at entry of every kernel_launch call —
// guaranteed by static init for the first call and by k_out's trailing
// re-zero for all subsequent calls/replays.
__device__ __align__(16) __half g_table_h[VOCAB * D]; // fp16 shadow (32.8 MB)
__device__ __align__(16) __half g_W[NC * VOCAB];      // class-token histogram (4.1 MB)
__device__ __align__(16) float g_pp[KS * NC * D];     // split-K partials (26.2 MB)
__device__ float g_proto[NC * D];   // normalized prototypes (after k_reduce)
__device__ float g_cnt[NC];         // per-class support-row counts
__device__ float g_qemb[QN * D];    // query embeddings (mean-pooled)
__device__ float g_q2[QN];          // ||q||^2

__device__ __forceinline__ unsigned smem_u32(const void* p) {
    unsigned a;
    asm("{ .reg .u64 t; cvta.to.shared.u64 t, %1; cvt.u32.u64 %0, t; }"
        : "=r"(a) : "l"(p));
    return a;
}

// ---------------------------------------------------------------- kernel 1
// Fused front end, role-split by blockIdx.x:
//  [0, 1024)        query gather on the fp32 table (2 rows per 256-thr block)
//  [1024, 9024)     table fp32 -> fp16 convert
//  [9024, 10048)    support class-token histogram into g_W (+ class counts)
// All three roles are mutually independent (gather reads fp32 table, not the
// shadow; hist relies on the W=0 entry invariant).
__global__ __launch_bounds__(256) void k_front(
    const int*   __restrict__ q_toks,
    const int*   __restrict__ s_toks,
    const int*   __restrict__ labels,
    const float* __restrict__ table)
{
    const int bid = blockIdx.x;
    const int tid = threadIdx.x;

    if (bid < FB_GATHER) {
        // ---- query gather: half-block h handles row 2*bid + h ----
        const int h    = tid >> 7;           // 0 or 1
        const int lt   = tid & 127;          // lane within half-block
        const int row  = bid * 2 + h;

        __shared__ int sh_tok[2][TOK];
        __shared__ float sp[8];
        if (lt < TOK)
            sh_tok[h][lt] = q_toks[(size_t)row * TOK + lt];
        __syncthreads();

        float a0 = 0.f, a1 = 0.f, a2 = 0.f, a3 = 0.f;
        #pragma unroll 8
        for (int j = 0; j < TOK; ++j) {
            const float4* r = (const float4*)(table + (size_t)sh_tok[h][j] * D);
            float4 x = r[lt];
            a0 += x.x; a1 += x.y; a2 += x.z; a3 += x.w;
        }
        const float s = 1.0f / (float)TOK;
        a0 *= s; a1 *= s; a2 *= s; a3 *= s;
        ((float4*)(g_qemb + (size_t)row * D))[lt] = make_float4(a0, a1, a2, a3);

        float qq = a0*a0 + a1*a1 + a2*a2 + a3*a3;
        #pragma unroll
        for (int o = 16; o > 0; o >>= 1)
            qq += __shfl_down_sync(0xFFFFFFFFu, qq, o);
        if ((tid & 31) == 0) sp[tid >> 5] = qq;
        __syncthreads();
        if (lt == 0)
            g_q2[row] = sp[h * 4] + sp[h * 4 + 1] + sp[h * 4 + 2] + sp[h * 4 + 3];
    } else if (bid < FB_CONV) {
        // ---- convert: 8 fp32 elems -> 8 fp16 per thread ----
        const int i = (bid - FB_GATHER) * 256 + tid;   // 8-elem group id
        const float4* sp4 = (const float4*)table;
        float4 a = sp4[2 * i];
        float4 b = sp4[2 * i + 1];
        __half2 h0 = __floats2half2_rn(a.x, a.y);
        __half2 h1 = __floats2half2_rn(a.z, a.w);
        __half2 h2 = __floats2half2_rn(b.x, b.y);
        __half2 h3 = __floats2half2_rn(b.z, b.w);
        uint4 o;
        o.x = *(const unsigned*)&h0;
        o.y = *(const unsigned*)&h1;
        o.z = *(const unsigned*)&h2;
        o.w = *(const unsigned*)&h3;
        ((uint4*)g_table_h)[i] = o;
    } else {
        // ---- histogram: one support token per thread ----
        const int t   = (bid - FB_CONV) * 256 + tid;   // < SN*TOK
        const int row = t >> 6;
        const int c   = labels[row];
        const int v   = s_toks[t];
        const int idx = c * VOCAB + v;
        __half2* p = (__half2*)(g_W + (idx & ~1));
        const __half2 one = (idx & 1)
            ? __halves2half2(__ushort_as_half(0), __float2half(1.0f))
            : __halves2half2(__float2half(1.0f), __ushort_as_half(0));
        atomicAdd(p, one);
        if ((t & 63) == 0) atomicAdd(&g_cnt[c], 1.0f);
    }
}

// ---------------------------------------------------------------- kernel 2
// Split-K tensor-core GEMM. 256 threads = 8 warps: wr = warp&3 row group
// (16 rows), wn = warp>>2 col group (64 cols) of the 64x128 block tile.
// Register-prefetched staging; partials stored (no atomics) to g_pp.
__global__ __launch_bounds__(256) void k_pgemm()
{
    __shared__ __half sA[64 * 24];    // 64x16 W tile, row stride 24 halves
    __shared__ __half sB[16 * 136];   // 16x128 table tile, row stride 136

    const int bn = (blockIdx.x & (NT - 1)) * 128;       // n offset
    const int kb = blockIdx.x / NT;                     // k-split index
    const int k0 = kb * KCHUNK;
    const int tid  = threadIdx.x;
    const int warp = tid >> 5;
    const int lane = tid & 31;
    const int wr   = warp & 3;        // row group
    const int wn   = warp >> 2;       // col group
    const int g    = lane >> 2;       // 0..7
    const int tg   = lane & 3;        // 0..3

    // Staging addressing: A by threads <128 (uint4), B by all 256 (uint4).
    const int arow  = (tid & 127) >> 1;     // 0..63
    const int acol8 = (tid & 1) * 8;        // 0 or 8
    const int brow  = tid >> 4;             // 0..15
    const int bcol8 = (tid & 15) * 8;       // 0..120

    const __half* aSrc = g_W + (size_t)arow * VOCAB + k0 + acol8;
    const __half* bSrc = g_table_h + (size_t)(k0 + brow) * D + bn + bcol8;

    // ldmatrix addressing
    const int am = lane >> 3, ar = lane & 7;
    const unsigned aAddr = smem_u32(sA + (wr * 16 + ar + 8 * (am & 1)) * 24
                                       + 8 * (am >> 1));
    const unsigned bAddr = smem_u32(sB + (lane & 15) * 136 + wn * 64);

    float acc[8][4];
    #pragma unroll
    for (int s = 0; s < 8; ++s)
        acc[s][0] = acc[s][1] = acc[s][2] = acc[s][3] = 0.0f;

    // Prologue: tile 0 into registers.
    uint4 va = make_uint4(0, 0, 0, 0);
    if (tid < 128) va = *(const uint4*)(aSrc);
    uint4 vb = *(const uint4*)(bSrc);

    for (int it = 0; it < NITER; ++it) {
        __syncthreads();                    // prior step's smem reads done
        if (tid < 128) *(uint4*)(sA + arow * 24 + acol8) = va;
        *(uint4*)(sB + brow * 136 + bcol8) = vb;
        __syncthreads();

        // Prefetch next tile (clamped redundant re-load on last iter).
        const int kn = min((it + 1) * 16, KCHUNK - 16);
        if (tid < 128) va = *(const uint4*)(aSrc + kn);
        vb = *(const uint4*)(bSrc + (size_t)kn * D);

        unsigned a0, a1, a2, a3;
        asm volatile("ldmatrix.sync.aligned.m8n8.x4.shared.b16 {%0,%1,%2,%3}, [%4];"
                     : "=r"(a0), "=r"(a1), "=r"(a2), "=r"(a3) : "r"(aAddr));
        #pragma unroll
        for (int s = 0; s < 8; ++s) {
            unsigned b0, b1;
            asm volatile("ldmatrix.sync.aligned.m8n8.x2.trans.shared.b16 {%0,%1}, [%2];"
                         : "=r"(b0), "=r"(b1) : "r"(bAddr + s * 16));
            asm volatile(
                "mma.sync.aligned.m16n8k16.row.col.f32.f16.f16.f32 "
                "{%0,%1,%2,%3}, {%4,%5,%6,%7}, {%8,%9}, {%0,%1,%2,%3};"
                : "+f"(acc[s][0]), "+f"(acc[s][1]), "+f"(acc[s][2]), "+f"(acc[s][3])
                : "r"(a0), "r"(a1), "r"(a2), "r"(a3), "r"(b0), "r"(b1));
        }
    }

    // Epilogue: plain stores to this split's private partial slice.
    float* base = g_pp + (size_t)kb * NC * D;
    #pragma unroll
    for (int s = 0; s < 8; ++s) {
        const int col = bn + wn * 64 + s * 8 + tg * 2;
        *(float2*)(base + (wr * 16 + g) * D + col)     =
            make_float2(acc[s][0], acc[s][1]);
        *(float2*)(base + (wr * 16 + g + 8) * D + col) =
            make_float2(acc[s][2], acc[s][3]);
    }
}

// ---------------------------------------------------------------- kernel 3
// Fold split-K partials AND the 1/(64*cnt) normalization:
// g_proto[i] = (sum_s g_pp[s][i]) / (64 * max(cnt[i/D], 1)).
__global__ __launch_bounds__(256) void k_reduce()
{
    const int i = blockIdx.x * blockDim.x + threadIdx.x;   // < NC*D
    float a = 0.0f;
    #pragma unroll 8
    for (int s = 0; s < KS; ++s) a += g_pp[(size_t)s * NC * D + i];
    const int c = i >> 9;                                  // i / D
    g_proto[i] = a / (64.0f * fmaxf(g_cnt[c], 1.0f));
}

// ---------------------------------------------------------------- kernel 4
// 16 queries x 64 classes per block; protos are fully normalized.
// Trailing duty: re-zero g_W and g_cnt for the next kernel_launch call
// (neither is read by this kernel, so in-kernel ordering is irrelevant).
__global__ __launch_bounds__(256) void k_out(float* __restrict__ out)
{
    const int c  = threadIdx.x & 63;
    const int g  = threadIdx.x >> 6;              // 0..3
    const int q0 = blockIdx.x * 16 + g * 4;

    const float4* pr = (const float4*)(g_proto + (size_t)c * D);
    const float4* qa = (const float4*)(g_qemb + (size_t)(q0 + 0) * D);
    const float4* qb = (const float4*)(g_qemb + (size_t)(q0 + 1) * D);
    const float4* qc = (const float4*)(g_qemb + (size_t)(q0 + 2) * D);
    const float4* qd = (const float4*)(g_qemb + (size_t)(q0 + 3) * D);

    float d0 = 0.f, d1 = 0.f, d2 = 0.f, d3 = 0.f, pp = 0.f;
    #pragma unroll 4
    for (int i = 0; i < D / 4; ++i) {
        float4 p = pr[i];
        float4 a = qa[i], b = qb[i], x = qc[i], y = qd[i];
        pp += p.x*p.x + p.y*p.y + p.z*p.z + p.w*p.w;
        d0 += p.x*a.x + p.y*a.y + p.z*a.z + p.w*a.w;
        d1 += p.x*b.x + p.y*b.y + p.z*b.z + p.w*b.w;
        d2 += p.x*x.x + p.y*x.y + p.z*x.z + p.w*x.w;
        d3 += p.x*y.x + p.y*y.y + p.z*y.z + p.w*y.w;
    }
    out[(size_t)(q0 + 0) * NC + c] = -(g_q2[q0 + 0] + pp - 2.0f * d0);
    out[(size_t)(q0 + 1) * NC + c] = -(g_q2[q0 + 1] + pp - 2.0f * d1);
    out[(size_t)(q0 + 2) * NC + c] = -(g_q2[q0 + 2] + pp - 2.0f * d2);
    out[(size_t)(q0 + 3) * NC + c] = -(g_q2[q0 + 3] + pp - 2.0f * d3);

    // Restore the W=0 / cnt=0 entry invariant for the next call.
    const int t = blockIdx.x * 256 + threadIdx.x;          // < 32768
    uint4* w4 = (uint4*)g_W;                               // 256000 uint4
    for (int i = t; i < NC * VOCAB / 8; i += 32768)
        w4[i] = make_uint4(0, 0, 0, 0);
    if (t < NC) g_cnt[t] = 0.0f;
}

// ----------------------------------------------------------------
extern "C" void kernel_launch(void* const* d_in, const int* in_sizes, int n_in,
                              void* d_out, int out_size)
{
    // JAX x64 disabled -> "int64" tensors are int32 on the wire.
    const int*   query   = (const int*)d_in[0];
    const int*   support = (const int*)d_in[1];
    const int*   labels  = (const int*)d_in[2];
    const float* table   = (const float*)d_in[3];
    float* out = (float*)d_out;

    k_front<<<FB_HIST, 256>>>(query, support, labels, table);
    k_pgemm<<<NT * KS, 256>>>();
    k_reduce<<<NC * D / 256, 256>>>();
    k_out<<<QN / 16, 256>>>(out);
}

// round 12
// speedup vs baseline: 1.5761x; 1.3471x over previous
#include <cuda_runtime.h>
#include <cuda_fp16.h>

static constexpr int TOK   = 64;     // tokens per sequence
static constexpr int D     = 512;    // embedding dim
static constexpr int NC    = 64;     // classes
static constexpr int QN    = 2048;   // queries
static constexpr int SN    = 4096;   // supports
static constexpr int VOCAB = 32000;

// GEMM: proto_raw[64 x 32000-hist] @ table_h[32000 x 512]
static constexpr int KS     = 200;           // K splits
static constexpr int KCHUNK = VOCAB / KS;    // 160
static constexpr int NITER  = KCHUNK / 16;   // 10
static constexpr int NT     = 4;             // N tiles of 128  (grid = 800)

// k_front role boundaries (block index)
static constexpr int FB_GATHER = 1024;               // 1024 blocks x 2 query rows
static constexpr int FB_CONV   = FB_GATHER + 8000;   // 8000 convert blocks
static constexpr int FB_HIST   = FB_CONV + 1024;     // 1024 hist blocks

// k_out tiling: 64q x 64c x 64d per block, 8 d-splits
static constexpr int DS    = 8;              // d splits (64 dims each)
static constexpr int QB    = QN / 64;        // 32 q blocks
static constexpr int TP    = 68;             // padded tile row stride (floats)

// Scratch (__device__ globals; zero-initialized at module load).
// INVARIANT: g_W and g_cnt are ZERO at entry of every kernel_launch call —
// module-load zeros for call 1; k_reduce re-zeros W, k_out re-zeros cnt for
// subsequent calls/replays.
__device__ __align__(16) __half g_table_h[VOCAB * D]; // fp16 shadow (32.8 MB)
__device__ __align__(16) __half g_W[NC * VOCAB];      // class-token histogram (4.1 MB)
__device__ __align__(16) float g_pp[KS * NC * D];     // split-K partials (26.2 MB)
__device__ float g_proto[NC * D];   // normalized prototypes (after k_reduce)
__device__ float g_cnt[NC];         // per-class support-row counts
__device__ float g_qemb[QN * D];    // query embeddings (mean-pooled)
__device__ float g_q2[QN];          // ||q||^2

__device__ __forceinline__ unsigned smem_u32(const void* p) {
    unsigned a;
    asm("{ .reg .u64 t; cvta.to.shared.u64 t, %1; cvt.u32.u64 %0, t; }"
        : "=r"(a) : "l"(p));
    return a;
}

// ---------------------------------------------------------------- kernel 1
// Fused front end, role-split by blockIdx.x:
//  [0, 1024)        query gather on the fp32 table (2 rows per 256-thr block)
//  [1024, 9024)     table fp32 -> fp16 convert
//  [9024, 10048)    support class-token histogram into g_W (+ class counts)
__global__ __launch_bounds__(256) void k_front(
    const int*   __restrict__ q_toks,
    const int*   __restrict__ s_toks,
    const int*   __restrict__ labels,
    const float* __restrict__ table)
{
    const int bid = blockIdx.x;
    const int tid = threadIdx.x;

    if (bid < FB_GATHER) {
        const int h    = tid >> 7;           // 0 or 1
        const int lt   = tid & 127;          // lane within half-block
        const int row  = bid * 2 + h;

        __shared__ int sh_tok[2][TOK];
        __shared__ float sp[8];
        if (lt < TOK)
            sh_tok[h][lt] = q_toks[(size_t)row * TOK + lt];
        __syncthreads();

        float a0 = 0.f, a1 = 0.f, a2 = 0.f, a3 = 0.f;
        #pragma unroll 8
        for (int j = 0; j < TOK; ++j) {
            const float4* r = (const float4*)(table + (size_t)sh_tok[h][j] * D);
            float4 x = r[lt];
            a0 += x.x; a1 += x.y; a2 += x.z; a3 += x.w;
        }
        const float s = 1.0f / (float)TOK;
        a0 *= s; a1 *= s; a2 *= s; a3 *= s;
        ((float4*)(g_qemb + (size_t)row * D))[lt] = make_float4(a0, a1, a2, a3);

        float qq = a0*a0 + a1*a1 + a2*a2 + a3*a3;
        #pragma unroll
        for (int o = 16; o > 0; o >>= 1)
            qq += __shfl_down_sync(0xFFFFFFFFu, qq, o);
        if ((tid & 31) == 0) sp[tid >> 5] = qq;
        __syncthreads();
        if (lt == 0)
            g_q2[row] = sp[h * 4] + sp[h * 4 + 1] + sp[h * 4 + 2] + sp[h * 4 + 3];
    } else if (bid < FB_CONV) {
        const int i = (bid - FB_GATHER) * 256 + tid;   // 8-elem group id
        const float4* sp4 = (const float4*)table;
        float4 a = sp4[2 * i];
        float4 b = sp4[2 * i + 1];
        __half2 h0 = __floats2half2_rn(a.x, a.y);
        __half2 h1 = __floats2half2_rn(a.z, a.w);
        __half2 h2 = __floats2half2_rn(b.x, b.y);
        __half2 h3 = __floats2half2_rn(b.z, b.w);
        uint4 o;
        o.x = *(const unsigned*)&h0;
        o.y = *(const unsigned*)&h1;
        o.z = *(const unsigned*)&h2;
        o.w = *(const unsigned*)&h3;
        ((uint4*)g_table_h)[i] = o;
    } else {
        const int t   = (bid - FB_CONV) * 256 + tid;   // < SN*TOK
        const int row = t >> 6;
        const int c   = labels[row];
        const int v   = s_toks[t];
        const int idx = c * VOCAB + v;
        __half2* p = (__half2*)(g_W + (idx & ~1));
        const __half2 one = (idx & 1)
            ? __halves2half2(__ushort_as_half(0), __float2half(1.0f))
            : __halves2half2(__float2half(1.0f), __ushort_as_half(0));
        atomicAdd(p, one);
        if ((t & 63) == 0) atomicAdd(&g_cnt[c], 1.0f);
    }
}

// ---------------------------------------------------------------- kernel 2
// Split-K tensor-core GEMM (proven in R9/R10).
__global__ __launch_bounds__(256) void k_pgemm()
{
    __shared__ __half sA[64 * 24];
    __shared__ __half sB[16 * 136];

    const int bn = (blockIdx.x & (NT - 1)) * 128;
    const int kb = blockIdx.x / NT;
    const int k0 = kb * KCHUNK;
    const int tid  = threadIdx.x;
    const int warp = tid >> 5;
    const int lane = tid & 31;
    const int wr   = warp & 3;
    const int wn   = warp >> 2;
    const int g    = lane >> 2;
    const int tg   = lane & 3;

    const int arow  = (tid & 127) >> 1;
    const int acol8 = (tid & 1) * 8;
    const int brow  = tid >> 4;
    const int bcol8 = (tid & 15) * 8;

    const __half* aSrc = g_W + (size_t)arow * VOCAB + k0 + acol8;
    const __half* bSrc = g_table_h + (size_t)(k0 + brow) * D + bn + bcol8;

    const int am = lane >> 3, ar = lane & 7;
    const unsigned aAddr = smem_u32(sA + (wr * 16 + ar + 8 * (am & 1)) * 24
                                       + 8 * (am >> 1));
    const unsigned bAddr = smem_u32(sB + (lane & 15) * 136 + wn * 64);

    float acc[8][4];
    #pragma unroll
    for (int s = 0; s < 8; ++s)
        acc[s][0] = acc[s][1] = acc[s][2] = acc[s][3] = 0.0f;

    uint4 va = make_uint4(0, 0, 0, 0);
    if (tid < 128) va = *(const uint4*)(aSrc);
    uint4 vb = *(const uint4*)(bSrc);

    for (int it = 0; it < NITER; ++it) {
        __syncthreads();
        if (tid < 128) *(uint4*)(sA + arow * 24 + acol8) = va;
        *(uint4*)(sB + brow * 136 + bcol8) = vb;
        __syncthreads();

        const int kn = min((it + 1) * 16, KCHUNK - 16);
        if (tid < 128) va = *(const uint4*)(aSrc + kn);
        vb = *(const uint4*)(bSrc + (size_t)kn * D);

        unsigned a0, a1, a2, a3;
        asm volatile("ldmatrix.sync.aligned.m8n8.x4.shared.b16 {%0,%1,%2,%3}, [%4];"
                     : "=r"(a0), "=r"(a1), "=r"(a2), "=r"(a3) : "r"(aAddr));
        #pragma unroll
        for (int s = 0; s < 8; ++s) {
            unsigned b0, b1;
            asm volatile("ldmatrix.sync.aligned.m8n8.x2.trans.shared.b16 {%0,%1}, [%2];"
                         : "=r"(b0), "=r"(b1) : "r"(bAddr + s * 16));
            asm volatile(
                "mma.sync.aligned.m16n8k16.row.col.f32.f16.f16.f32 "
                "{%0,%1,%2,%3}, {%4,%5,%6,%7}, {%8,%9}, {%0,%1,%2,%3};"
                : "+f"(acc[s][0]), "+f"(acc[s][1]), "+f"(acc[s][2]), "+f"(acc[s][3])
                : "r"(a0), "r"(a1), "r"(a2), "r"(a3), "r"(b0), "r"(b1));
        }
    }

    float* base = g_pp + (size_t)kb * NC * D;
    #pragma unroll
    for (int s = 0; s < 8; ++s) {
        const int col = bn + wn * 64 + s * 8 + tg * 2;
        *(float2*)(base + (wr * 16 + g) * D + col)     =
            make_float2(acc[s][0], acc[s][1]);
        *(float2*)(base + (wr * 16 + g + 8) * D + col) =
            make_float2(acc[s][2], acc[s][3]);
    }
}

// ---------------------------------------------------------------- kernel 3
// Fold split-K partials + 1/(64*cnt) normalization into g_proto.
// Also: init out[q][c] = -q2[q] (base term for k_out's atomic partials)
// and re-zero g_W (not touched by this kernel) for the next call.
__global__ __launch_bounds__(256) void k_reduce(float* __restrict__ out)
{
    const int t = blockIdx.x * blockDim.x + threadIdx.x;   // < 32768 = NC*D
    float a = 0.0f;
    #pragma unroll 8
    for (int s = 0; s < KS; ++s) a += g_pp[(size_t)s * NC * D + t];
    const int c = t >> 9;                                  // t / D
    g_proto[t] = a / (64.0f * fmaxf(g_cnt[c], 1.0f));

    // out init: QN*NC = 131072 elements, 4 per thread
    #pragma unroll
    for (int r = 0; r < 4; ++r) {
        const int idx = t + r * 32768;
        out[idx] = -g_q2[idx >> 6];
    }

    // W re-zero: g_W = NC*VOCAB/8 = 256000 uint4 (NOT 512K — guard bound!)
    uint4* w4 = (uint4*)g_W;
    #pragma unroll
    for (int r = 0; r < 8; ++r) {
        const int idx = t + r * 32768;
        if (idx < NC * VOCAB / 8) w4[idx] = make_uint4(0, 0, 0, 0);
    }
}

// ---------------------------------------------------------------- kernel 4
// Distance GEMM, smem-tiled + d-split: block = 64q x 64c x 64d.
// Grid = 32 q-blocks x 8 d-splits = 256. 256 threads, 4q x 4c register tile.
// Contribution per split: 2*dot_s - p2_s, atomically added onto the -q2 base.
// Trailing duty: zero g_cnt (not read here) for the next call.
__global__ __launch_bounds__(256) void k_out(float* __restrict__ out)
{
    __shared__ __align__(16) float q_s[64 * TP];   // 64 x 64, stride 68
    __shared__ __align__(16) float p_s[64 * TP];
    __shared__ float s_pp[NC];

    const int tid = threadIdx.x;
    const int q0  = (blockIdx.x >> 3) * 64;       // q block
    const int d0  = (blockIdx.x & 7) * 64;        // d split

    // Stage tiles: 64 rows x 16 float4 each; 4 float4 per thread, coalesced.
    #pragma unroll
    for (int r = 0; r < 4; ++r) {
        const int idx  = tid + r * 256;           // < 1024
        const int row  = idx >> 4;
        const int col4 = idx & 15;
        ((float4*)(q_s + row * TP))[col4] =
            ((const float4*)(g_qemb + (size_t)(q0 + row) * D + d0))[col4];
        ((float4*)(p_s + row * TP))[col4] =
            ((const float4*)(g_proto + (size_t)row * D + d0))[col4];
    }
    __syncthreads();

    const int tq = tid >> 4;       // 0..15 -> q rows [4tq, 4tq+4)
    const int tc = tid & 15;       // c rows tc, tc+16, tc+32, tc+48

    float acc[4][4];
    #pragma unroll
    for (int i = 0; i < 4; ++i)
        acc[i][0] = acc[i][1] = acc[i][2] = acc[i][3] = 0.0f;
    float pa0 = 0.f, pa1 = 0.f, pa2 = 0.f, pa3 = 0.f;

    #pragma unroll 4
    for (int d4 = 0; d4 < 16; ++d4) {
        float4 pv[4];
        #pragma unroll
        for (int j = 0; j < 4; ++j)
            pv[j] = ((const float4*)(p_s + (tc + 16 * j) * TP))[d4];
        if (tq == 0) {   // p2 partials (one owner per class)
            pa0 += pv[0].x*pv[0].x + pv[0].y*pv[0].y + pv[0].z*pv[0].z + pv[0].w*pv[0].w;
            pa1 += pv[1].x*pv[1].x + pv[1].y*pv[1].y + pv[1].z*pv[1].z + pv[1].w*pv[1].w;
            pa2 += pv[2].x*pv[2].x + pv[2].y*pv[2].y + pv[2].z*pv[2].z + pv[2].w*pv[2].w;
            pa3 += pv[3].x*pv[3].x + pv[3].y*pv[3].y + pv[3].z*pv[3].z + pv[3].w*pv[3].w;
        }
        #pragma unroll
        for (int i = 0; i < 4; ++i) {
            const float4 qv = ((const float4*)(q_s + (4 * tq + i) * TP))[d4];
            #pragma unroll
            for (int j = 0; j < 4; ++j)
                acc[i][j] += qv.x*pv[j].x + qv.y*pv[j].y
                           + qv.z*pv[j].z + qv.w*pv[j].w;
        }
    }

    if (tq == 0) {
        s_pp[tc]      = pa0;
        s_pp[tc + 16] = pa1;
        s_pp[tc + 32] = pa2;
        s_pp[tc + 48] = pa3;
    }
    __syncthreads();

    #pragma unroll
    for (int i = 0; i < 4; ++i) {
        const int q = q0 + 4 * tq + i;
        #pragma unroll
        for (int j = 0; j < 4; ++j) {
            const int c = tc + 16 * j;
            atomicAdd(out + (size_t)q * NC + c, 2.0f * acc[i][j] - s_pp[c]);
        }
    }

    // cnt re-zero for next call (cnt is not read by this kernel).
    const int t = blockIdx.x * 256 + tid;
    if (t < NC) g_cnt[t] = 0.0f;
}

// ----------------------------------------------------------------
extern "C" void kernel_launch(void* const* d_in, const int* in_sizes, int n_in,
                              void* d_out, int out_size)
{
    // JAX x64 disabled -> "int64" tensors are int32 on the wire.
    const int*   query   = (const int*)d_in[0];
    const int*   support = (const int*)d_in[1];
    const int*   labels  = (const int*)d_in[2];
    const float* table   = (const float*)d_in[3];
    float* out = (float*)d_out;

    k_front<<<FB_HIST, 256>>>(query, support, labels, table);
    k_pgemm<<<NT * KS, 256>>>();
    k_reduce<<<NC * D / 256, 256>>>(out);
    k_out<<<QB * DS, 256>>>(out);
}

// round 13
// speedup vs baseline: 1.8548x; 1.1768x over previous
#include <cuda_runtime.h>
#include <cuda_fp16.h>

static constexpr int TOK   = 64;     // tokens per sequence
static constexpr int D     = 512;    // embedding dim
static constexpr int NC    = 64;     // classes
static constexpr int QN    = 2048;   // queries
static constexpr int SN    = 4096;   // supports
static constexpr int VOCAB = 32000;

// GEMM: proto_raw[64 x 32000-hist] @ table_h[32000 x 512]
static constexpr int KS     = 125;           // K splits
static constexpr int KCHUNK = VOCAB / KS;    // 256
static constexpr int NITER  = KCHUNK / 16;   // 16
static constexpr int NT     = 4;             // N tiles of 128 (pgemm grid = 500)

// k_front role boundaries (block index): convert then hist
static constexpr int FB_CONV = 8000;
static constexpr int FB_HIST = FB_CONV + 1024;

// k_mid role boundaries: pgemm then query gather (2 rows/block)
static constexpr int MB_GEMM   = NT * KS;            // 500
static constexpr int MB_GATHER = MB_GEMM + QN / 2;   // + 1024

// k_out tiling: 64q x 64c x 64d per block, 8 d-splits
static constexpr int DS = 8;                 // d splits (64 dims each)
static constexpr int QB = QN / 64;           // 32 q blocks
static constexpr int TP = 68;                // padded tile row stride (floats)

// Scratch (__device__ globals; zero-initialized at module load).
// INVARIANT: g_W and g_cnt are ZERO at entry of every kernel_launch call —
// module-load zeros for call 1; k_reduce re-zeros W, k_out re-zeros cnt.
__device__ __align__(16) __half g_table_h[VOCAB * D]; // fp16 shadow (32.8 MB)
__device__ __align__(16) __half g_W[NC * VOCAB];      // class-token histogram (4.1 MB)
__device__ __align__(16) float g_pp[KS * NC * D];     // split-K partials (16.4 MB)
__device__ float g_proto[NC * D];   // normalized prototypes (after k_reduce)
__device__ float g_cnt[NC];         // per-class support-row counts
__device__ float g_qemb[QN * D];    // query embeddings (mean-pooled)
__device__ float g_q2[QN];          // ||q||^2

__device__ __forceinline__ unsigned smem_u32(const void* p) {
    unsigned a;
    asm("{ .reg .u64 t; cvta.to.shared.u64 t, %1; cvt.u32.u64 %0, t; }"
        : "=r"(a) : "l"(p));
    return a;
}

// ---------------------------------------------------------------- kernel 1
// Front end: [0,8000) table fp32 -> fp16 convert; [8000,9024) support hist.
__global__ __launch_bounds__(256) void k_front(
    const int*   __restrict__ s_toks,
    const int*   __restrict__ labels,
    const float* __restrict__ table)
{
    const int bid = blockIdx.x;
    const int tid = threadIdx.x;

    if (bid < FB_CONV) {
        // ---- convert: 8 fp32 elems -> 8 fp16 per thread ----
        const int i = bid * 256 + tid;               // 8-elem group id
        const float4* sp4 = (const float4*)table;
        float4 a = sp4[2 * i];
        float4 b = sp4[2 * i + 1];
        __half2 h0 = __floats2half2_rn(a.x, a.y);
        __half2 h1 = __floats2half2_rn(a.z, a.w);
        __half2 h2 = __floats2half2_rn(b.x, b.y);
        __half2 h3 = __floats2half2_rn(b.z, b.w);
        uint4 o;
        o.x = *(const unsigned*)&h0;
        o.y = *(const unsigned*)&h1;
        o.z = *(const unsigned*)&h2;
        o.w = *(const unsigned*)&h3;
        ((uint4*)g_table_h)[i] = o;
    } else {
        // ---- histogram: one support token per thread ----
        const int t   = (bid - FB_CONV) * 256 + tid; // < SN*TOK
        const int row = t >> 6;
        const int c   = labels[row];
        const int v   = s_toks[t];
        const int idx = c * VOCAB + v;
        __half2* p = (__half2*)(g_W + (idx & ~1));
        const __half2 one = (idx & 1)
            ? __halves2half2(__ushort_as_half(0), __float2half(1.0f))
            : __halves2half2(__float2half(1.0f), __ushort_as_half(0));
        atomicAdd(p, one);
        if ((t & 63) == 0) atomicAdd(&g_cnt[c], 1.0f);
    }
}

// ---------------------------------------------------------------- kernel 2
// Mid stage, role-split: [0,500) split-K tensor-core proto GEMM;
// [500,1524) query gather on the fp16 shadow (2 rows per block).
// Both roles depend only on k_front outputs; they overlap in one wave.
__global__ __launch_bounds__(256) void k_mid(const int* __restrict__ q_toks)
{
    const int tid = threadIdx.x;

    if (blockIdx.x < MB_GEMM) {
        // ================= proto GEMM (proven R9-R12 core) =================
        __shared__ __half sA[64 * 24];
        __shared__ __half sB[16 * 136];

        const int bn = (blockIdx.x & (NT - 1)) * 128;
        const int kb = blockIdx.x / NT;
        const int k0 = kb * KCHUNK;
        const int warp = tid >> 5;
        const int lane = tid & 31;
        const int wr   = warp & 3;
        const int wn   = warp >> 2;
        const int g    = lane >> 2;
        const int tg   = lane & 3;

        const int arow  = (tid & 127) >> 1;
        const int acol8 = (tid & 1) * 8;
        const int brow  = tid >> 4;
        const int bcol8 = (tid & 15) * 8;

        const __half* aSrc = g_W + (size_t)arow * VOCAB + k0 + acol8;
        const __half* bSrc = g_table_h + (size_t)(k0 + brow) * D + bn + bcol8;

        const int am = lane >> 3, ar = lane & 7;
        const unsigned aAddr = smem_u32(sA + (wr * 16 + ar + 8 * (am & 1)) * 24
                                           + 8 * (am >> 1));
        const unsigned bAddr = smem_u32(sB + (lane & 15) * 136 + wn * 64);

        float acc[8][4];
        #pragma unroll
        for (int s = 0; s < 8; ++s)
            acc[s][0] = acc[s][1] = acc[s][2] = acc[s][3] = 0.0f;

        uint4 va = make_uint4(0, 0, 0, 0);
        if (tid < 128) va = *(const uint4*)(aSrc);
        uint4 vb = *(const uint4*)(bSrc);

        for (int it = 0; it < NITER; ++it) {
            __syncthreads();
            if (tid < 128) *(uint4*)(sA + arow * 24 + acol8) = va;
            *(uint4*)(sB + brow * 136 + bcol8) = vb;
            __syncthreads();

            const int kn = min((it + 1) * 16, KCHUNK - 16);
            if (tid < 128) va = *(const uint4*)(aSrc + kn);
            vb = *(const uint4*)(bSrc + (size_t)kn * D);

            unsigned a0, a1, a2, a3;
            asm volatile("ldmatrix.sync.aligned.m8n8.x4.shared.b16 {%0,%1,%2,%3}, [%4];"
                         : "=r"(a0), "=r"(a1), "=r"(a2), "=r"(a3) : "r"(aAddr));
            #pragma unroll
            for (int s = 0; s < 8; ++s) {
                unsigned b0, b1;
                asm volatile("ldmatrix.sync.aligned.m8n8.x2.trans.shared.b16 {%0,%1}, [%2];"
                             : "=r"(b0), "=r"(b1) : "r"(bAddr + s * 16));
                asm volatile(
                    "mma.sync.aligned.m16n8k16.row.col.f32.f16.f16.f32 "
                    "{%0,%1,%2,%3}, {%4,%5,%6,%7}, {%8,%9}, {%0,%1,%2,%3};"
                    : "+f"(acc[s][0]), "+f"(acc[s][1]), "+f"(acc[s][2]), "+f"(acc[s][3])
                    : "r"(a0), "r"(a1), "r"(a2), "r"(a3), "r"(b0), "r"(b1));
            }
        }

        float* base = g_pp + (size_t)kb * NC * D;
        #pragma unroll
        for (int s = 0; s < 8; ++s) {
            const int col = bn + wn * 64 + s * 8 + tg * 2;
            *(float2*)(base + (wr * 16 + g) * D + col)     =
                make_float2(acc[s][0], acc[s][1]);
            *(float2*)(base + (wr * 16 + g + 8) * D + col) =
                make_float2(acc[s][2], acc[s][3]);
        }
    } else {
        // ================= query gather on fp16 shadow =================
        const int bid = blockIdx.x - MB_GEMM;
        const int h   = tid >> 7;            // 0 or 1
        const int lt  = tid & 127;           // lane within half-block
        const int row = bid * 2 + h;

        __shared__ int sh_tok[2][TOK];
        __shared__ float sp[8];
        if (lt < TOK)
            sh_tok[h][lt] = q_toks[(size_t)row * TOK + lt];
        __syncthreads();

        float a0 = 0.f, a1 = 0.f, a2 = 0.f, a3 = 0.f;
        #pragma unroll 8
        for (int j = 0; j < TOK; ++j) {
            const uint2* r = (const uint2*)(g_table_h + (size_t)sh_tok[h][j] * D);
            uint2 v = r[lt];                           // 4 halves
            float2 f0 = __half22float2(*(const __half2*)&v.x);
            float2 f1 = __half22float2(*(const __half2*)&v.y);
            a0 += f0.x; a1 += f0.y; a2 += f1.x; a3 += f1.y;
        }
        const float s = 1.0f / (float)TOK;
        a0 *= s; a1 *= s; a2 *= s; a3 *= s;
        ((float4*)(g_qemb + (size_t)row * D))[lt] = make_float4(a0, a1, a2, a3);

        float qq = a0*a0 + a1*a1 + a2*a2 + a3*a3;
        #pragma unroll
        for (int o = 16; o > 0; o >>= 1)
            qq += __shfl_down_sync(0xFFFFFFFFu, qq, o);
        if ((tid & 31) == 0) sp[tid >> 5] = qq;
        __syncthreads();
        if (lt == 0)
            g_q2[row] = sp[h * 4] + sp[h * 4 + 1] + sp[h * 4 + 2] + sp[h * 4 + 3];
    }
}

// ---------------------------------------------------------------- kernel 3
// Fold split-K partials + 1/(64*cnt) normalization into g_proto.
// Also: init out[q][c] = -q2[q], and re-zero g_W for the next call.
__global__ __launch_bounds__(256) void k_reduce(float* __restrict__ out)
{
    const int t = blockIdx.x * blockDim.x + threadIdx.x;   // < 32768 = NC*D
    float a = 0.0f;
    #pragma unroll 5
    for (int s = 0; s < KS; ++s) a += g_pp[(size_t)s * NC * D + t];
    const int c = t >> 9;                                  // t / D
    g_proto[t] = a / (64.0f * fmaxf(g_cnt[c], 1.0f));

    // out init: QN*NC = 131072 elements, 4 per thread
    #pragma unroll
    for (int r = 0; r < 4; ++r) {
        const int idx = t + r * 32768;
        out[idx] = -g_q2[idx >> 6];
    }

    // W re-zero: g_W = NC*VOCAB/8 = 256000 uint4 (guarded)
    uint4* w4 = (uint4*)g_W;
    #pragma unroll
    for (int r = 0; r < 8; ++r) {
        const int idx = t + r * 32768;
        if (idx < NC * VOCAB / 8) w4[idx] = make_uint4(0, 0, 0, 0);
    }
}

// ---------------------------------------------------------------- kernel 4
// Distance GEMM, smem-tiled + d-split (proven R12). Trailing: zero g_cnt.
__global__ __launch_bounds__(256) void k_out(float* __restrict__ out)
{
    __shared__ __align__(16) float q_s[64 * TP];
    __shared__ __align__(16) float p_s[64 * TP];
    __shared__ float s_pp[NC];

    const int tid = threadIdx.x;
    const int q0  = (blockIdx.x >> 3) * 64;       // q block
    const int d0  = (blockIdx.x & 7) * 64;        // d split

    #pragma unroll
    for (int r = 0; r < 4; ++r) {
        const int idx  = tid + r * 256;
        const int row  = idx >> 4;
        const int col4 = idx & 15;
        ((float4*)(q_s + row * TP))[col4] =
            ((const float4*)(g_qemb + (size_t)(q0 + row) * D + d0))[col4];
        ((float4*)(p_s + row * TP))[col4] =
            ((const float4*)(g_proto + (size_t)row * D + d0))[col4];
    }
    __syncthreads();

    const int tq = tid >> 4;
    const int tc = tid & 15;

    float acc[4][4];
    #pragma unroll
    for (int i = 0; i < 4; ++i)
        acc[i][0] = acc[i][1] = acc[i][2] = acc[i][3] = 0.0f;
    float pa0 = 0.f, pa1 = 0.f, pa2 = 0.f, pa3 = 0.f;

    #pragma unroll 4
    for (int d4 = 0; d4 < 16; ++d4) {
        float4 pv[4];
        #pragma unroll
        for (int j = 0; j < 4; ++j)
            pv[j] = ((const float4*)(p_s + (tc + 16 * j) * TP))[d4];
        if (tq == 0) {
            pa0 += pv[0].x*pv[0].x + pv[0].y*pv[0].y + pv[0].z*pv[0].z + pv[0].w*pv[0].w;
            pa1 += pv[1].x*pv[1].x + pv[1].y*pv[1].y + pv[1].z*pv[1].z + pv[1].w*pv[1].w;
            pa2 += pv[2].x*pv[2].x + pv[2].y*pv[2].y + pv[2].z*pv[2].z + pv[2].w*pv[2].w;
            pa3 += pv[3].x*pv[3].x + pv[3].y*pv[3].y + pv[3].z*pv[3].z + pv[3].w*pv[3].w;
        }
        #pragma unroll
        for (int i = 0; i < 4; ++i) {
            const float4 qv = ((const float4*)(q_s + (4 * tq + i) * TP))[d4];
            #pragma unroll
            for (int j = 0; j < 4; ++j)
                acc[i][j] += qv.x*pv[j].x + qv.y*pv[j].y
                           + qv.z*pv[j].z + qv.w*pv[j].w;
        }
    }

    if (tq == 0) {
        s_pp[tc]      = pa0;
        s_pp[tc + 16] = pa1;
        s_pp[tc + 32] = pa2;
        s_pp[tc + 48] = pa3;
    }
    __syncthreads();

    #pragma unroll
    for (int i = 0; i < 4; ++i) {
        const int q = q0 + 4 * tq + i;
        #pragma unroll
        for (int j = 0; j < 4; ++j) {
            const int c = tc + 16 * j;
            atomicAdd(out + (size_t)q * NC + c, 2.0f * acc[i][j] - s_pp[c]);
        }
    }

    const int t = blockIdx.x * 256 + tid;
    if (t < NC) g_cnt[t] = 0.0f;
}

// ----------------------------------------------------------------
extern "C" void kernel_launch(void* const* d_in, const int* in_sizes, int n_in,
                              void* d_out, int out_size)
{
    // JAX x64 disabled -> "int64" tensors are int32 on the wire.
    const int*   query   = (const int*)d_in[0];
    const int*   support = (const int*)d_in[1];
    const int*   labels  = (const int*)d_in[2];
    const float* table   = (const float*)d_in[3];
    float* out = (float*)d_out;

    k_front<<<FB_HIST, 256>>>(support, labels, table);  // convert + hist
    k_mid<<<MB_GATHER, 256>>>(query);                   // proto GEMM ∥ q gather
    k_reduce<<<NC * D / 256, 256>>>(out);               // fold splits + out init
    k_out<<<QB * DS, 256>>>(out);                       // distances
}